// round 9
// baseline (speedup 1.0000x reference)
#include <cuda_runtime.h>

#define D 128
#define KN 32
#define MAXB 20000

__device__ float g_u[D];
__device__ float g_v[D];
__device__ float g_M[D * D];
__device__ float g_agg[MAXB * D];

// packed f32x2 FMA (Blackwell): acc = a*b + acc lanewise (exact fp32, 2 lanes)
#define FMA2(acc, a, b) \
    asm("fma.rn.f32x2 %0, %1, %2, %0;" : "+l"(acc) : "l"(a), "l"(b))

// ---------------------------------------------------------------------------
// Kernel P1: u/v precompute. 2 blocks x 128 threads (R5-measured form).
// ---------------------------------------------------------------------------
__global__ __launch_bounds__(128) void prep_uv(
    const float* __restrict__ kernel0,
    const float* __restrict__ kernel1,
    const float* __restrict__ aw) {
    int t    = threadIdx.x;
    int lane = t & 31;
    int w    = t >> 5;

    const float* mat = (blockIdx.x == 0) ? kernel1 : kernel0;
    const float* a   = aw + blockIdx.x * D;
    float*       out = (blockIdx.x == 0) ? g_u : g_v;

    float4 av = ((const float4*)a)[lane];
    const float4* m4 = (const float4*)mat;
#pragma unroll
    for (int j = 0; j < 32; ++j) {
        int r = w * 32 + j;
        float4 x = m4[r * 32 + lane];
        float s = x.x * av.x + x.y * av.y + x.z * av.z + x.w * av.w;
#pragma unroll
        for (int o = 16; o > 0; o >>= 1) s += __shfl_xor_sync(0xffffffffu, s, o);
        if (lane == 0) out[r] = s;
    }
}

// ---------------------------------------------------------------------------
// Kernel P2: M precompute — direct coalesced LDG of nw (L2-resident after
// first wave), no 64KB staging. 128 blocks x 128 threads.
// ---------------------------------------------------------------------------
__global__ __launch_bounds__(128) void prep_M(
    const float* __restrict__ kernel1,
    const float* __restrict__ nw) {
    __shared__ float krow[D];

    int b = blockIdx.x;
    int t = threadIdx.x;

    krow[t] = kernel1[b * D + t];
    __syncthreads();

    float acc = 0.f;
#pragma unroll 8
    for (int j = 0; j < D; ++j)
        acc += krow[j] * __ldg(&nw[j * D + t]);
    g_M[b * D + t] = acc;
}

// ---------------------------------------------------------------------------
// Kernel A: per-target attention — register-resident rows, 256 threads
// (8 warps x 4 rows each; lower regs/thread -> more resident warps).
// ---------------------------------------------------------------------------
__global__ __launch_bounds__(256) void attn_kernel(
    const float* __restrict__ features,
    const int* __restrict__ node,
    const int* __restrict__ neigh,
    int B) {
    __shared__ float scores[KN];
    __shared__ float wts[KN];
    __shared__ float part[8 * D];   // per-warp partial sums (4 KB)

    int b = blockIdx.x;
    if (b >= B) return;
    int tid  = threadIdx.x;
    int lane = tid & 31;
    int w    = tid >> 5;            // 0..7

    const float4* f4 = (const float4*)features;

    // gather 4 rows per warp into registers: row k(it) = it*8 + w
    float4 x[4];
#pragma unroll
    for (int it = 0; it < 4; ++it) {
        int k  = it * 8 + w;
        int nb = __ldg(&neigh[b * KN + k]);
        x[it]  = f4[(size_t)nb * 32 + lane];
    }

    // sn = dot(node_row, v): per-warp redundant, registers only
    int nd = __ldg(&node[b]);
    float4 fv = f4[(size_t)nd * 32 + lane];
    float4 vv = ((const float4*)g_v)[lane];
    float sn = fv.x * vv.x + fv.y * vv.y + fv.z * vv.z + fv.w * vv.w;
#pragma unroll
    for (int o = 16; o > 0; o >>= 1) sn += __shfl_xor_sync(0xffffffffu, sn, o);

    // scores from registers
    float4 uu = ((const float4*)g_u)[lane];
#pragma unroll
    for (int it = 0; it < 4; ++it) {
        float s = x[it].x * uu.x + x[it].y * uu.y + x[it].z * uu.z + x[it].w * uu.w;
#pragma unroll
        for (int o = 16; o > 0; o >>= 1) s += __shfl_xor_sync(0xffffffffu, s, o);
        if (lane == 0) {
            float t = s + sn;
            scores[it * 8 + w] = (t > 0.f) ? t : 0.2f * t;   // leaky_relu
        }
    }
    __syncthreads();

    // softmax over K=32 (warp 0)
    if (w == 0) {
        float sc = scores[lane];
        float m = sc;
#pragma unroll
        for (int o = 16; o > 0; o >>= 1) m = fmaxf(m, __shfl_xor_sync(0xffffffffu, m, o));
        float e = __expf(sc - m);
        float den = e;
#pragma unroll
        for (int o = 16; o > 0; o >>= 1) den += __shfl_xor_sync(0xffffffffu, den, o);
        wts[lane] = e / den;
    }
    __syncthreads();

    // weighted aggregate from registers: per-warp partial over its 4 rows
    float4 p = make_float4(0.f, 0.f, 0.f, 0.f);
#pragma unroll
    for (int it = 0; it < 4; ++it) {
        float wk = wts[it * 8 + w];
        p.x += wk * x[it].x;
        p.y += wk * x[it].y;
        p.z += wk * x[it].z;
        p.w += wk * x[it].w;
    }
    ((float4*)part)[w * 32 + lane] = p;
    __syncthreads();

    // cross-warp reduce: thread tid (<128) sums column tid over 8 warps
    if (tid < D) {
        float acc = 0.f;
#pragma unroll
        for (int ww = 0; ww < 8; ++ww) acc += part[ww * D + tid];
        g_agg[b * D + tid] = acc;
    }
}

// ---------------------------------------------------------------------------
// Kernel G: out = agg @ M. 128 threads; 16-row register tile (two 8-row
// transpose slabs) + packed FMA2 inner loop. Launched 4th (ncu slot).
// ---------------------------------------------------------------------------
__global__ __launch_bounds__(128) void out_gemm(float* __restrict__ out, int B) {
    extern __shared__ float sm[];
    float* Ms  = sm;             // D*D floats (64 KB)
    float* aT0 = sm + D * D;     // [d*8 + r], rows 0..7  (4 KB)
    float* aT1 = aT0 + D * 8;    // [d*8 + r], rows 8..15 (4 KB)

    int tid = threadIdx.x;

    float4*       Ms4 = (float4*)Ms;
    const float4* gM4 = (const float4*)g_M;
#pragma unroll
    for (int it = 0; it < 32; ++it) Ms4[it * 128 + tid] = gM4[it * 128 + tid];

    int ngroups = (B + 15) >> 4;       // 16 rows per group
    for (int g = blockIdx.x; g < ngroups; g += gridDim.x) {
        int r0 = g << 4;

        float v[16];
#pragma unroll
        for (int r = 0; r < 16; ++r) {
            int row = r0 + r;
            v[r] = (row < B) ? g_agg[row * D + tid] : 0.f;
        }
        __syncthreads();
        ((float4*)aT0)[tid * 2]     = make_float4(v[0],  v[1],  v[2],  v[3]);
        ((float4*)aT0)[tid * 2 + 1] = make_float4(v[4],  v[5],  v[6],  v[7]);
        ((float4*)aT1)[tid * 2]     = make_float4(v[8],  v[9],  v[10], v[11]);
        ((float4*)aT1)[tid * 2 + 1] = make_float4(v[12], v[13], v[14], v[15]);
        __syncthreads();

        unsigned long long a01 = 0ull, a23 = 0ull, a45 = 0ull, a67 = 0ull;
        unsigned long long a89 = 0ull, aAB = 0ull, aCD = 0ull, aEF = 0ull;
#pragma unroll 8
        for (int d = 0; d < D; ++d) {
            float m = Ms[d * D + tid];
            unsigned long long mm;
            asm("mov.b64 %0, {%1, %1};" : "=l"(mm) : "f"(m));
            ulonglong2 p0 = *((const ulonglong2*)(aT0 + d * 8));
            ulonglong2 p1 = *((const ulonglong2*)(aT0 + d * 8 + 4));
            ulonglong2 p2 = *((const ulonglong2*)(aT1 + d * 8));
            ulonglong2 p3 = *((const ulonglong2*)(aT1 + d * 8 + 4));
            FMA2(a01, p0.x, mm);
            FMA2(a23, p0.y, mm);
            FMA2(a45, p1.x, mm);
            FMA2(a67, p1.y, mm);
            FMA2(a89, p2.x, mm);
            FMA2(aAB, p2.y, mm);
            FMA2(aCD, p3.x, mm);
            FMA2(aEF, p3.y, mm);
        }

        float r_[16];
        asm("mov.b64 {%0, %1}, %2;" : "=f"(r_[0]),  "=f"(r_[1])  : "l"(a01));
        asm("mov.b64 {%0, %1}, %2;" : "=f"(r_[2]),  "=f"(r_[3])  : "l"(a23));
        asm("mov.b64 {%0, %1}, %2;" : "=f"(r_[4]),  "=f"(r_[5])  : "l"(a45));
        asm("mov.b64 {%0, %1}, %2;" : "=f"(r_[6]),  "=f"(r_[7])  : "l"(a67));
        asm("mov.b64 {%0, %1}, %2;" : "=f"(r_[8]),  "=f"(r_[9])  : "l"(a89));
        asm("mov.b64 {%0, %1}, %2;" : "=f"(r_[10]), "=f"(r_[11]) : "l"(aAB));
        asm("mov.b64 {%0, %1}, %2;" : "=f"(r_[12]), "=f"(r_[13]) : "l"(aCD));
        asm("mov.b64 {%0, %1}, %2;" : "=f"(r_[14]), "=f"(r_[15]) : "l"(aEF));
#pragma unroll
        for (int r = 0; r < 16; ++r) {
            int row = r0 + r;
            if (row < B) out[row * D + tid] = r_[r];
        }
    }
}

// ---------------------------------------------------------------------------
extern "C" void kernel_launch(void* const* d_in, const int* in_sizes, int n_in,
                              void* d_out, int out_size) {
    const float* features = (const float*)d_in[0];
    const int*   node     = (const int*)d_in[1];
    const int*   neigh    = (const int*)d_in[2];
    const float* kern0    = (const float*)d_in[3];
    const float* kern1    = (const float*)d_in[4];
    const float* aw       = (const float*)d_in[5];
    const float* nw       = (const float*)d_in[6];
    float*       out      = (float*)d_out;

    int B = in_sizes[1];
    if (B > MAXB) B = MAXB;

    // 4 launches; gemm is 4th (ncu capture slot).
    prep_uv<<<2, D>>>(kern0, kern1, aw);               // 1
    prep_M<<<D, D>>>(kern1, nw);                       // 2
    attn_kernel<<<B, 256>>>(features, node, neigh, B); // 3
    const int gemm_smem = (D * D + 2 * D * 8) * sizeof(float);   // 72 KB
    cudaFuncSetAttribute(out_gemm, cudaFuncAttributeMaxDynamicSharedMemorySize, gemm_smem);
    out_gemm<<<444, D, gemm_smem>>>(out, B);           // 4 (profiled)
}

// round 10
// speedup vs baseline: 1.2040x; 1.2040x over previous
#include <cuda_runtime.h>

#define D 128
#define KN 32
#define MAXB 20000
#define GROWS 160          // rows per gemm block
#define GPAD 164           // padded row-dim for transposed agg tile

__device__ float g_u[D];
__device__ float g_v[D];
__device__ float g_M[D * D];
__device__ float g_agg[MAXB * D];

// packed f32x2 FMA (Blackwell): acc = a*b + acc lanewise (exact fp32, 2 lanes)
#define FMA2(acc, a, b) \
    asm("fma.rn.f32x2 %0, %1, %2, %0;" : "+l"(acc) : "l"(a), "l"(b))

// ---------------------------------------------------------------------------
// Kernel P1: u/v precompute. 2 blocks x 128 threads (measured form).
// ---------------------------------------------------------------------------
__global__ __launch_bounds__(128) void prep_uv(
    const float* __restrict__ kernel0,
    const float* __restrict__ kernel1,
    const float* __restrict__ aw) {
    int t    = threadIdx.x;
    int lane = t & 31;
    int w    = t >> 5;

    const float* mat = (blockIdx.x == 0) ? kernel1 : kernel0;
    const float* a   = aw + blockIdx.x * D;
    float*       out = (blockIdx.x == 0) ? g_u : g_v;

    float4 av = ((const float4*)a)[lane];
    const float4* m4 = (const float4*)mat;
#pragma unroll
    for (int j = 0; j < 32; ++j) {
        int r = w * 32 + j;
        float4 x = m4[r * 32 + lane];
        float s = x.x * av.x + x.y * av.y + x.z * av.z + x.w * av.w;
#pragma unroll
        for (int o = 16; o > 0; o >>= 1) s += __shfl_xor_sync(0xffffffffu, s, o);
        if (lane == 0) out[r] = s;
    }
}

// ---------------------------------------------------------------------------
// Kernel P2: M precompute — R8-measured smem-staging form (~8.5us).
// ---------------------------------------------------------------------------
__global__ __launch_bounds__(128) void prep_M(
    const float* __restrict__ kernel1,
    const float* __restrict__ nw) {
    extern __shared__ float psm[];
    float* nws  = psm;          // D*D floats (64KB)
    float* krow = psm + D * D;  // D floats

    int b = blockIdx.x;
    int t = threadIdx.x;

    krow[t] = kernel1[b * D + t];
    const float4* nw4  = (const float4*)nw;
    float4*       nws4 = (float4*)nws;
#pragma unroll
    for (int it = 0; it < 32; ++it)
        nws4[it * 128 + t] = nw4[it * 128 + t];
    __syncthreads();

    float acc = 0.f;
#pragma unroll 16
    for (int j = 0; j < D; ++j)
        acc += krow[j] * nws[j * D + t];
    g_M[b * D + t] = acc;
}

// ---------------------------------------------------------------------------
// Kernel A: per-target attention — exact R8-measured form (52.8us).
// 128 threads; warp w, iteration it holds row (it*4+w) in registers.
// ---------------------------------------------------------------------------
__global__ __launch_bounds__(128) void attn_kernel(
    const float* __restrict__ features,
    const int* __restrict__ node,
    const int* __restrict__ neigh,
    int B) {
    __shared__ float scores[KN];
    __shared__ float wts[KN];
    __shared__ float part[4 * D];

    int b = blockIdx.x;
    if (b >= B) return;
    int tid  = threadIdx.x;
    int lane = tid & 31;
    int w    = tid >> 5;

    const float4* f4 = (const float4*)features;

    float4 x[8];
#pragma unroll
    for (int it = 0; it < 8; ++it) {
        int k  = it * 4 + w;
        int nb = __ldg(&neigh[b * KN + k]);
        x[it]  = f4[(size_t)nb * 32 + lane];
    }

    int nd = __ldg(&node[b]);
    float4 fv = f4[(size_t)nd * 32 + lane];
    float4 vv = ((const float4*)g_v)[lane];
    float sn = fv.x * vv.x + fv.y * vv.y + fv.z * vv.z + fv.w * vv.w;
#pragma unroll
    for (int o = 16; o > 0; o >>= 1) sn += __shfl_xor_sync(0xffffffffu, sn, o);

    float4 uu = ((const float4*)g_u)[lane];
#pragma unroll
    for (int it = 0; it < 8; ++it) {
        float s = x[it].x * uu.x + x[it].y * uu.y + x[it].z * uu.z + x[it].w * uu.w;
#pragma unroll
        for (int o = 16; o > 0; o >>= 1) s += __shfl_xor_sync(0xffffffffu, s, o);
        if (lane == 0) {
            float t = s + sn;
            scores[it * 4 + w] = (t > 0.f) ? t : 0.2f * t;
        }
    }
    __syncthreads();

    if (w == 0) {
        float sc = scores[lane];
        float m = sc;
#pragma unroll
        for (int o = 16; o > 0; o >>= 1) m = fmaxf(m, __shfl_xor_sync(0xffffffffu, m, o));
        float e = __expf(sc - m);
        float den = e;
#pragma unroll
        for (int o = 16; o > 0; o >>= 1) den += __shfl_xor_sync(0xffffffffu, den, o);
        wts[lane] = e / den;
    }
    __syncthreads();

    float4 p = make_float4(0.f, 0.f, 0.f, 0.f);
#pragma unroll
    for (int it = 0; it < 8; ++it) {
        float wk = wts[it * 4 + w];
        p.x += wk * x[it].x;
        p.y += wk * x[it].y;
        p.z += wk * x[it].z;
        p.w += wk * x[it].w;
    }
    ((float4*)part)[w * 32 + lane] = p;
    __syncthreads();

    float acc = part[tid] + part[D + tid] + part[2 * D + tid] + part[3 * D + tid];
    g_agg[b * D + tid] = acc;
}

// ---------------------------------------------------------------------------
// Kernel G v3: out = agg @ M. 320 threads (20 ty x 16 tx), block = 160 rows,
// 8x8 register tile per thread, FMA2. agg tile staged TRANSPOSED in smem
// (aTs[d][row], pad 164). 125 blocks = single wave. smem ~146 KB.
// ---------------------------------------------------------------------------
__global__ __launch_bounds__(320) void out_gemm(float* __restrict__ out, int B) {
    extern __shared__ float sm[];
    float* Ms  = sm;             // D*D floats (64 KB)
    float* aTs = sm + D * D;     // D * GPAD floats (82 KB), [d*GPAD + row]

    int tid = threadIdx.x;
    int r0  = blockIdx.x * GROWS;

    // stage M
    float4*       Ms4 = (float4*)Ms;
    const float4* gM4 = (const float4*)g_M;
    for (int i = tid; i < (D * D) / 4; i += 320) Ms4[i] = gM4[i];

    // stage agg tile transposed: 2 threads per row, each covers 64 d
    {
        int row  = tid >> 1;           // 0..159
        int half = tid & 1;            // d-half: 0 or 1
        bool rv  = (r0 + row) < B;
        const float4* ga = (const float4*)g_agg + (size_t)(r0 + row) * 32 + half * 16;
#pragma unroll
        for (int i = 0; i < 16; ++i) {
            float4 f = rv ? ga[i] : make_float4(0.f, 0.f, 0.f, 0.f);
            int d = half * 64 + i * 4;
            aTs[(d + 0) * GPAD + row] = f.x;
            aTs[(d + 1) * GPAD + row] = f.y;
            aTs[(d + 2) * GPAD + row] = f.z;
            aTs[(d + 3) * GPAD + row] = f.w;
        }
    }
    __syncthreads();

    int ty = tid >> 4;   // 0..19  -> rows ty*8..ty*8+7
    int tx = tid & 15;   // 0..15  -> cols tx*8..tx*8+7

    unsigned long long acc[8][4];
#pragma unroll
    for (int i = 0; i < 8; ++i)
#pragma unroll
        for (int j = 0; j < 4; ++j) acc[i][j] = 0ull;

#pragma unroll 4
    for (int d = 0; d < D; ++d) {
        float4 a0 = *(const float4*)(aTs + d * GPAD + ty * 8);
        float4 a1 = *(const float4*)(aTs + d * GPAD + ty * 8 + 4);
        ulonglong2 m01 = *(const ulonglong2*)(Ms + d * D + tx * 8);
        ulonglong2 m23 = *(const ulonglong2*)(Ms + d * D + tx * 8 + 4);
        float ar[8] = {a0.x, a0.y, a0.z, a0.w, a1.x, a1.y, a1.z, a1.w};
#pragma unroll
        for (int i = 0; i < 8; ++i) {
            unsigned long long mm;
            asm("mov.b64 %0, {%1, %1};" : "=l"(mm) : "f"(ar[i]));
            FMA2(acc[i][0], m01.x, mm);
            FMA2(acc[i][1], m01.y, mm);
            FMA2(acc[i][2], m23.x, mm);
            FMA2(acc[i][3], m23.y, mm);
        }
    }

    // epilogue: unpack + store
#pragma unroll
    for (int i = 0; i < 8; ++i) {
        int row = r0 + ty * 8 + i;
        if (row < B) {
            float r_[8];
            asm("mov.b64 {%0, %1}, %2;" : "=f"(r_[0]), "=f"(r_[1]) : "l"(acc[i][0]));
            asm("mov.b64 {%0, %1}, %2;" : "=f"(r_[2]), "=f"(r_[3]) : "l"(acc[i][1]));
            asm("mov.b64 {%0, %1}, %2;" : "=f"(r_[4]), "=f"(r_[5]) : "l"(acc[i][2]));
            asm("mov.b64 {%0, %1}, %2;" : "=f"(r_[6]), "=f"(r_[7]) : "l"(acc[i][3]));
            float4* o4 = (float4*)(out + (size_t)row * D + tx * 8);
            o4[0] = make_float4(r_[0], r_[1], r_[2], r_[3]);
            o4[1] = make_float4(r_[4], r_[5], r_[6], r_[7]);
        }
    }
}

// ---------------------------------------------------------------------------
extern "C" void kernel_launch(void* const* d_in, const int* in_sizes, int n_in,
                              void* d_out, int out_size) {
    const float* features = (const float*)d_in[0];
    const int*   node     = (const int*)d_in[1];
    const int*   neigh    = (const int*)d_in[2];
    const float* kern0    = (const float*)d_in[3];
    const float* kern1    = (const float*)d_in[4];
    const float* aw       = (const float*)d_in[5];
    const float* nw       = (const float*)d_in[6];
    float*       out      = (float*)d_out;

    int B = in_sizes[1];
    if (B > MAXB) B = MAXB;

    prep_uv<<<2, D>>>(kern0, kern1, aw);                       // 1

    const int prepM_smem = (D * D + D) * sizeof(float);        // ~66 KB
    cudaFuncSetAttribute(prep_M, cudaFuncAttributeMaxDynamicSharedMemorySize, prepM_smem);
    prep_M<<<D, D, prepM_smem>>>(kern1, nw);                   // 2

    attn_kernel<<<B, D>>>(features, node, neigh, B);           // 3

    const int gemm_smem = (D * D + D * GPAD) * sizeof(float);  // ~146 KB
    cudaFuncSetAttribute(out_gemm, cudaFuncAttributeMaxDynamicSharedMemorySize, gemm_smem);
    int gblocks = (B + GROWS - 1) / GROWS;                     // 125 for B=20000
    out_gemm<<<gblocks, 320, gemm_smem>>>(out, B);             // 4 (profiled)
}